// round 2
// baseline (speedup 1.0000x reference)
#include <cuda_runtime.h>
#include <math.h>

// Problem constants (fixed by the dataset)
#define B 8
#define N 2048
#define D 384
#define TWO_D 768
#define KNN_K 8
#define BN_ROWS (B * N)      // 16384
#define EPS 1e-5f
#define NEG_SLOPE 0.2f

// ---------------- scratch (device globals; no allocation allowed) -----------
__device__ float g_Y[BN_ROWS * TWO_D];     // [y1 | yd] per point (50.3 MB)
__device__ float g_H[BN_ROWS * D];         // max-pooled features (25.2 MB)
__device__ float g_Wcat[D * TWO_D];        // K x N layout: Wcat[k*768 + j]
__device__ float g_W2T[D * D];             // W2T[k*384 + j] = w2[j][k]
__device__ int   g_idx[BN_ROWS * KNN_K];   // knn indices (within-batch)

// ---------------- weight prep ----------------------------------------------
// Wcat[k][j] = w1[j][k]                    for j < 384      (w1a^T)
//            = w1[j-384][384+k] - w1[j-384][k]  for j >= 384 (w1b^T - w1a^T)
__global__ void prep_weights_kernel(const float* __restrict__ w1,
                                    const float* __restrict__ w2) {
    int i = blockIdx.x * blockDim.x + threadIdx.x;
    if (i < D * TWO_D) {
        int k = i / TWO_D;
        int j = i % TWO_D;
        float v;
        if (j < D) {
            v = w1[j * TWO_D + k];
        } else {
            int jj = j - D;
            v = w1[jj * TWO_D + D + k] - w1[jj * TWO_D + k];
        }
        g_Wcat[i] = v;
    }
    if (i < D * D) {
        int k = i / D;
        int j = i % D;
        g_W2T[i] = w2[j * D + k];
    }
}

// ---------------- KNN (brute force, top-8 smallest squared distance) -------
// One block = 256 queries of one batch. Entire batch's points live in smem.
__global__ void knn_kernel(const float* __restrict__ center) {
    __shared__ float sc[N * 3];   // 24 KB
    int b = blockIdx.y;
    const float* cb = center + (size_t)b * N * 3;
    for (int i = threadIdx.x; i < N * 3; i += 256) sc[i] = cb[i];
    __syncthreads();

    int q = blockIdx.x * 256 + threadIdx.x;
    float qx = sc[q * 3 + 0];
    float qy = sc[q * 3 + 1];
    float qz = sc[q * 3 + 2];

    float bd[KNN_K];
    int   bi[KNN_K];
#pragma unroll
    for (int s = 0; s < KNN_K; s++) { bd[s] = 3.4e38f; bi[s] = 0; }

    for (int j = 0; j < N; j++) {
        float dx = sc[j * 3 + 0] - qx;
        float dy = sc[j * 3 + 1] - qy;
        float dz = sc[j * 3 + 2] - qz;
        float d = dx * dx + dy * dy + dz * dz;
        if (d < bd[KNN_K - 1]) {
            bd[KNN_K - 1] = d; bi[KNN_K - 1] = j;
#pragma unroll
            for (int s = KNN_K - 1; s > 0; s--) {
                if (bd[s] < bd[s - 1]) {
                    float td = bd[s]; bd[s] = bd[s - 1]; bd[s - 1] = td;
                    int   ti = bi[s]; bi[s] = bi[s - 1]; bi[s - 1] = ti;
                }
            }
        }
    }

    int base = (b * N + q) * KNN_K;
#pragma unroll
    for (int s = 0; s < KNN_K; s++) g_idx[base + s] = bi[s];
}

// ---------------- SGEMM: C(MxNn) = A(MxKk) * B(KkxNn), 128x128x8 tiles -----
// EPI=false: plain store. EPI=true: fused BN + LeakyReLU epilogue.
template <bool EPI>
__global__ void __launch_bounds__(256, 2)
sgemm_kernel(const float* __restrict__ A, const float* __restrict__ Bm,
             float* __restrict__ C, int M, int Nn, int Kk,
             const float* __restrict__ bng, const float* __restrict__ bnb,
             const float* __restrict__ bnm, const float* __restrict__ bnv) {
    __shared__ float As[8][128];
    __shared__ float Bs[8][128];

    int tid = threadIdx.x;
    int bx = blockIdx.x;   // along Nn
    int by = blockIdx.y;   // along M

    int a_r = tid >> 1;            // 0..127
    int a_c = (tid & 1) * 4;       // 0 or 4
    int b_r = tid >> 5;            // 0..7
    int b_c = (tid & 31) * 4;      // 0..124

    int ty = tid >> 4;             // 0..15
    int tx = tid & 15;             // 0..15

    float acc[8][8];
#pragma unroll
    for (int i = 0; i < 8; i++)
#pragma unroll
        for (int j = 0; j < 8; j++) acc[i][j] = 0.f;

    const float* Aptr = A + (size_t)(by * 128 + a_r) * Kk + a_c;
    const float* Bptr = Bm + (size_t)b_r * Nn + bx * 128 + b_c;

    for (int k0 = 0; k0 < Kk; k0 += 8) {
        float4 av = *(const float4*)(Aptr + k0);
        As[a_c + 0][a_r] = av.x;
        As[a_c + 1][a_r] = av.y;
        As[a_c + 2][a_r] = av.z;
        As[a_c + 3][a_r] = av.w;
        float4 bv = *(const float4*)(Bptr + (size_t)k0 * Nn);
        *(float4*)&Bs[b_r][b_c] = bv;
        __syncthreads();

#pragma unroll
        for (int k = 0; k < 8; k++) {
            float ra[8], rb[8];
#pragma unroll
            for (int i = 0; i < 8; i++) ra[i] = As[k][ty * 8 + i];
#pragma unroll
            for (int j = 0; j < 8; j++) rb[j] = Bs[k][tx * 8 + j];
#pragma unroll
            for (int i = 0; i < 8; i++)
#pragma unroll
                for (int j = 0; j < 8; j++) acc[i][j] += ra[i] * rb[j];
        }
        __syncthreads();
    }

    int row0 = by * 128 + ty * 8;
    int col0 = bx * 128 + tx * 8;

    if (EPI) {
        float s2[8], t2[8];
#pragma unroll
        for (int j = 0; j < 8; j++) {
            int c = col0 + j;
            float s = bng[c] * rsqrtf(bnv[c] + EPS);
            s2[j] = s;
            t2[j] = bnb[c] - bnm[c] * s;
        }
#pragma unroll
        for (int i = 0; i < 8; i++) {
            float* crow = C + (size_t)(row0 + i) * Nn + col0;
#pragma unroll
            for (int j = 0; j < 8; j++) {
                float v = acc[i][j] * s2[j] + t2[j];
                crow[j] = v > 0.f ? v : NEG_SLOPE * v;
            }
        }
    } else {
#pragma unroll
        for (int i = 0; i < 8; i++) {
            float* crow = C + (size_t)(row0 + i) * Nn + col0;
#pragma unroll
            for (int j = 0; j < 8; j++) crow[j] = acc[i][j];
        }
    }
}

// ---------------- gather + BN1 + LeakyReLU + max over K ---------------------
// One block per point (384 threads, one channel each).
// h[n][d] = max_k lrelu( s1[d]*(y1[idx_k][d] + yd[n][d]) + t1[d] )
__global__ void gather_max_kernel(const float* __restrict__ bng,
                                  const float* __restrict__ bnb,
                                  const float* __restrict__ bnm,
                                  const float* __restrict__ bnv) {
    int n = blockIdx.x;            // global point id 0..16383
    int b = n >> 11;               // /2048
    int d = threadIdx.x;           // 0..383

    __shared__ int sidx[KNN_K];
    if (d < KNN_K) sidx[d] = g_idx[n * KNN_K + d];
    __syncthreads();

    float s = bng[d] * rsqrtf(bnv[d] + EPS);
    float t = bnb[d] - bnm[d] * s;
    float v = g_Y[(size_t)n * TWO_D + D + d];   // yd part

    float best = -3.4e38f;
#pragma unroll
    for (int k = 0; k < KNN_K; k++) {
        int nb = b * N + sidx[k];
        float a = g_Y[(size_t)nb * TWO_D + d];  // y1 part
        float h = s * (a + v) + t;
        h = h > 0.f ? h : NEG_SLOPE * h;
        best = fmaxf(best, h);
    }
    g_H[(size_t)n * D + d] = best;
}

// ---------------- launch ----------------------------------------------------
extern "C" void kernel_launch(void* const* d_in, const int* in_sizes, int n_in,
                              void* d_out, int out_size) {
    const float* x      = (const float*)d_in[0];
    const float* center = (const float*)d_in[1];
    const float* w1     = (const float*)d_in[2];
    const float* w2     = (const float*)d_in[3];
    const float* bn1_g  = (const float*)d_in[4];
    const float* bn1_b  = (const float*)d_in[5];
    const float* bn1_m  = (const float*)d_in[6];
    const float* bn1_v  = (const float*)d_in[7];
    const float* bn2_g  = (const float*)d_in[8];
    const float* bn2_b  = (const float*)d_in[9];
    const float* bn2_m  = (const float*)d_in[10];
    const float* bn2_v  = (const float*)d_in[11];
    float* out = (float*)d_out;

    float *Yp, *Hp, *Wcatp, *W2Tp;
    cudaGetSymbolAddress((void**)&Yp, g_Y);
    cudaGetSymbolAddress((void**)&Hp, g_H);
    cudaGetSymbolAddress((void**)&Wcatp, g_Wcat);
    cudaGetSymbolAddress((void**)&W2Tp, g_W2T);

    // 1. weight prep
    prep_weights_kernel<<<(D * TWO_D + 255) / 256, 256>>>(w1, w2);

    // 2. KNN
    knn_kernel<<<dim3(N / 256, B), 256>>>(center);

    // 3. GEMM1: Y = X(16384x384) @ Wcat(384x768)
    sgemm_kernel<false><<<dim3(TWO_D / 128, BN_ROWS / 128), 256>>>(
        x, Wcatp, Yp, BN_ROWS, TWO_D, D, nullptr, nullptr, nullptr, nullptr);

    // 4. gather + BN1 + lrelu + max over K
    gather_max_kernel<<<BN_ROWS, D>>>(bn1_g, bn1_b, bn1_m, bn1_v);

    // 5. GEMM2: out = lrelu(bn2(H(16384x384) @ W2T(384x384)))
    sgemm_kernel<true><<<dim3(D / 128, BN_ROWS / 128), 256>>>(
        Hp, W2Tp, out, BN_ROWS, D, D, bn2_g, bn2_b, bn2_m, bn2_v);
}

// round 6
// speedup vs baseline: 1.4184x; 1.4184x over previous
#include <cuda_runtime.h>
#include <math.h>
#include <stdint.h>

// Problem constants
#define B 8
#define N 2048
#define D 384
#define TWO_D 768
#define KNN_K 8
#define BN_ROWS (B * N)      // 16384
#define EPS 1e-5f
#define NEG_SLOPE 0.2f

// ---------------- scratch (device globals; no allocation allowed) -----------
__device__ float g_Y[BN_ROWS * TWO_D];     // [y1 | yd] per point
__device__ float g_H[BN_ROWS * D];         // max-pooled features
__device__ float g_W1B[TWO_D * D];         // [n_out][k] layout for GEMM1 B
__device__ int   g_idx[BN_ROWS * KNN_K];   // knn indices (within-batch)

// ======================= helpers ============================================
__device__ __forceinline__ uint32_t smem_u32(const void* p) {
    uint32_t a;
    asm("{ .reg .u64 t; cvta.to.shared.u64 t, %1; cvt.u32.u64 %0, t; }"
        : "=r"(a) : "l"(p));
    return a;
}

#define CP_ASYNC16(smem, gptr) \
    asm volatile("cp.async.cg.shared.global [%0], [%1], 16;" \
        :: "r"(smem), "l"(gptr) : "memory")
#define CP_COMMIT() asm volatile("cp.async.commit_group;" ::: "memory")
#define CP_WAIT(n)  asm volatile("cp.async.wait_group %0;" :: "n"(n) : "memory")

#define MMA_TF32(d, a0, a1, a2, a3, b0, b1) \
    asm volatile("mma.sync.aligned.m16n8k8.row.col.f32.tf32.tf32.f32 " \
        "{%0,%1,%2,%3}, {%4,%5,%6,%7}, {%8,%9}, {%0,%1,%2,%3};" \
        : "+f"((d)[0]), "+f"((d)[1]), "+f"((d)[2]), "+f"((d)[3]) \
        : "r"(a0), "r"(a1), "r"(a2), "r"(a3), "r"(b0), "r"(b1))

__device__ __forceinline__ uint32_t tf32rn(float f) {
    uint32_t u;
    asm("cvt.rn.tf32.f32 %0, %1;" : "=r"(u) : "f"(f));
    return u;
}
// split x into hi (tf32) + lo (tf32 of residual)
__device__ __forceinline__ void tf32split(float x, uint32_t& hi, uint32_t& lo) {
    hi = tf32rn(x);
    lo = tf32rn(x - __uint_as_float(hi));
}

// ---------------- weight prep ----------------------------------------------
// g_W1B[j][k]: j<384: w1[j][k]; j>=384: w1[j-384][384+k] - w1[j-384][k]
__global__ void prep_weights_kernel(const float* __restrict__ w1) {
    int i = blockIdx.x * blockDim.x + threadIdx.x;
    if (i < TWO_D * D) {
        int j = i / D;
        int k = i % D;
        float v;
        if (j < D) v = w1[j * TWO_D + k];
        else       v = w1[(j - D) * TWO_D + D + k] - w1[(j - D) * TWO_D + k];
        g_W1B[i] = v;
    }
}

// ---------------- KNN (brute force, top-8) ----------------------------------
__global__ void knn_kernel(const float* __restrict__ center) {
    __shared__ float sc[N * 3];
    int b = blockIdx.y;
    const float* cb = center + (size_t)b * N * 3;
    for (int i = threadIdx.x; i < N * 3; i += 256) sc[i] = cb[i];
    __syncthreads();

    int q = blockIdx.x * 256 + threadIdx.x;
    float qx = sc[q * 3 + 0], qy = sc[q * 3 + 1], qz = sc[q * 3 + 2];

    float bd[KNN_K];
    int   bi[KNN_K];
#pragma unroll
    for (int s = 0; s < KNN_K; s++) { bd[s] = 3.4e38f; bi[s] = 0; }

    for (int j = 0; j < N; j++) {
        float dx = sc[j * 3 + 0] - qx;
        float dy = sc[j * 3 + 1] - qy;
        float dz = sc[j * 3 + 2] - qz;
        float d = dx * dx + dy * dy + dz * dz;
        if (d < bd[KNN_K - 1]) {
            bd[KNN_K - 1] = d; bi[KNN_K - 1] = j;
#pragma unroll
            for (int s = KNN_K - 1; s > 0; s--) {
                if (bd[s] < bd[s - 1]) {
                    float td = bd[s]; bd[s] = bd[s - 1]; bd[s - 1] = td;
                    int   ti = bi[s]; bi[s] = bi[s - 1]; bi[s - 1] = ti;
                }
            }
        }
    }
    int base = (b * N + q) * KNN_K;
#pragma unroll
    for (int s = 0; s < KNN_K; s++) g_idx[base + s] = bi[s];
}

// ---------------- 3xTF32 mma.sync GEMM --------------------------------------
// C(M x Nn) = A(M x 384) * Bm(Nn x 384)^T, fp32-accurate via tf32 hi/lo split:
// x*y ~= xh*yh + xh*yl + xl*yh. 128x128 block tile, 8 warps, each warp
// 32(M) x 64(N) = 2x8 grid of m16n8k8. K chunks of 32, double-buffered
// cp.async of raw fp32; split happens in registers at fragment load.
#define KC 32
#define ROWSTRIDE 36                       // floats
#define STAGE_BYTES (128 * ROWSTRIDE * 4)  // 18432 per operand
static const int GEMM_SMEM = 4 * STAGE_BYTES;   // 73728

template <bool EPI>
__global__ void __launch_bounds__(256)
mma_gemm_kernel(const float* __restrict__ A, const float* __restrict__ Bm,
                float* __restrict__ C, int Nn,
                const float* __restrict__ bng, const float* __restrict__ bnb,
                const float* __restrict__ bnm, const float* __restrict__ bnv) {
    extern __shared__ char dsm[];
    uint32_t sb = smem_u32(dsm);
    int tid = threadIdx.x;
    int lane = tid & 31;
    int wid = tid >> 5;
    int wm = wid >> 1;          // 0..3 -> M offset wm*32
    int wn = wid & 1;           // 0..1 -> N offset wn*64
    int n0 = blockIdx.x * 128;
    int m0 = blockIdx.y * 128;

    // smem layout: [A0][B0][A1][B1]
    const uint32_t AOFF[2] = {0u, 2u * STAGE_BYTES};
    const uint32_t BOFF[2] = {STAGE_BYTES, 3u * STAGE_BYTES};

    float acc[2][8][4];
#pragma unroll
    for (int mt = 0; mt < 2; mt++)
#pragma unroll
        for (int nt = 0; nt < 8; nt++)
#pragma unroll
            for (int q = 0; q < 4; q++) acc[mt][nt][q] = 0.f;

    // ---- prefetch chunk 0 ----
    {
#pragma unroll
        for (int r = 0; r < 4; r++) {
            int i = tid + r * 256;       // 0..1023
            int row = i >> 3;
            int c = i & 7;
            CP_ASYNC16(sb + AOFF[0] + row * (ROWSTRIDE * 4) + c * 16,
                       A + (size_t)(m0 + row) * D + c * 4);
            CP_ASYNC16(sb + BOFF[0] + row * (ROWSTRIDE * 4) + c * 16,
                       Bm + (size_t)(n0 + row) * D + c * 4);
        }
        CP_COMMIT();
    }

    for (int ch = 0; ch < D / KC; ch++) {
        int buf = ch & 1;
        if (ch + 1 < D / KC) {
            int nb = buf ^ 1;
            int k0 = (ch + 1) * KC;
#pragma unroll
            for (int r = 0; r < 4; r++) {
                int i = tid + r * 256;
                int row = i >> 3;
                int c = i & 7;
                CP_ASYNC16(sb + AOFF[nb] + row * (ROWSTRIDE * 4) + c * 16,
                           A + (size_t)(m0 + row) * D + k0 + c * 4);
                CP_ASYNC16(sb + BOFF[nb] + row * (ROWSTRIDE * 4) + c * 16,
                           Bm + (size_t)(n0 + row) * D + k0 + c * 4);
            }
            CP_COMMIT();
            CP_WAIT(1);
        } else {
            CP_WAIT(0);
        }
        __syncthreads();

        const char* As = dsm + AOFF[buf] + (wm * 32) * (ROWSTRIDE * 4);
        const char* Bs = dsm + BOFF[buf] + (wn * 64) * (ROWSTRIDE * 4);
        int rsel = (lane >> 2) * (ROWSTRIDE * 4);
        int csel = (lane & 3) * 4;

#pragma unroll
        for (int kk = 0; kk < KC; kk += 8) {
            // A fragments: raw load then hi/lo split in registers
            uint32_t ah[2][4], al[2][4];
#pragma unroll
            for (int mt = 0; mt < 2; mt++) {
                const char* p = As + (mt * 16) * (ROWSTRIDE * 4) + rsel + kk * 4 + csel;
                float r0 = *(const float*)(p);
                float r1 = *(const float*)(p + 8 * (ROWSTRIDE * 4));
                float r2 = *(const float*)(p + 16);
                float r3 = *(const float*)(p + 8 * (ROWSTRIDE * 4) + 16);
                tf32split(r0, ah[mt][0], al[mt][0]);
                tf32split(r1, ah[mt][1], al[mt][1]);
                tf32split(r2, ah[mt][2], al[mt][2]);
                tf32split(r3, ah[mt][3], al[mt][3]);
            }
#pragma unroll
            for (int nt = 0; nt < 8; nt++) {
                const char* p = Bs + (nt * 8) * (ROWSTRIDE * 4) + rsel + kk * 4 + csel;
                float b0 = *(const float*)(p);
                float b1 = *(const float*)(p + 16);
                uint32_t bh0, bl0, bh1, bl1;
                tf32split(b0, bh0, bl0);
                tf32split(b1, bh1, bl1);
#pragma unroll
                for (int mt = 0; mt < 2; mt++) {
                    MMA_TF32(acc[mt][nt], ah[mt][0], ah[mt][1], ah[mt][2], ah[mt][3], bh0, bh1);
                    MMA_TF32(acc[mt][nt], ah[mt][0], ah[mt][1], ah[mt][2], ah[mt][3], bl0, bl1);
                    MMA_TF32(acc[mt][nt], al[mt][0], al[mt][1], al[mt][2], al[mt][3], bh0, bh1);
                }
            }
        }
        __syncthreads();
    }

    // ---- epilogue ----
    int rbase = m0 + wm * 32 + (lane >> 2);
    int cbase = n0 + wn * 64 + (lane & 3) * 2;
#pragma unroll
    for (int nt = 0; nt < 8; nt++) {
        int col = cbase + nt * 8;
        float s0 = 1.f, t0 = 0.f, s1 = 1.f, t1 = 0.f;
        if (EPI) {
            s0 = bng[col] * rsqrtf(bnv[col] + EPS);
            t0 = bnb[col] - bnm[col] * s0;
            s1 = bng[col + 1] * rsqrtf(bnv[col + 1] + EPS);
            t1 = bnb[col + 1] - bnm[col + 1] * s1;
        }
#pragma unroll
        for (int mt = 0; mt < 2; mt++) {
            float2 lo2, hi2;
            if (EPI) {
                float v0 = acc[mt][nt][0] * s0 + t0;
                float v1 = acc[mt][nt][1] * s1 + t1;
                float v2 = acc[mt][nt][2] * s0 + t0;
                float v3 = acc[mt][nt][3] * s1 + t1;
                lo2.x = v0 > 0.f ? v0 : NEG_SLOPE * v0;
                lo2.y = v1 > 0.f ? v1 : NEG_SLOPE * v1;
                hi2.x = v2 > 0.f ? v2 : NEG_SLOPE * v2;
                hi2.y = v3 > 0.f ? v3 : NEG_SLOPE * v3;
            } else {
                lo2.x = acc[mt][nt][0]; lo2.y = acc[mt][nt][1];
                hi2.x = acc[mt][nt][2]; hi2.y = acc[mt][nt][3];
            }
            int row = rbase + mt * 16;
            *(float2*)(C + (size_t)row * Nn + col) = lo2;
            *(float2*)(C + (size_t)(row + 8) * Nn + col) = hi2;
        }
    }
}

// ---------------- gather + BN1 + LeakyReLU + max over K ---------------------
__global__ void gather_max_kernel(const float* __restrict__ bng,
                                  const float* __restrict__ bnb,
                                  const float* __restrict__ bnm,
                                  const float* __restrict__ bnv) {
    int n = blockIdx.x;
    int b = n >> 11;
    int d = threadIdx.x;

    __shared__ int sidx[KNN_K];
    if (d < KNN_K) sidx[d] = g_idx[n * KNN_K + d];
    __syncthreads();

    float s = bng[d] * rsqrtf(bnv[d] + EPS);
    float t = bnb[d] - bnm[d] * s;
    float v = g_Y[(size_t)n * TWO_D + D + d];

    float best = -3.4e38f;
#pragma unroll
    for (int k = 0; k < KNN_K; k++) {
        int nb = b * N + sidx[k];
        float a = g_Y[(size_t)nb * TWO_D + d];
        float h = s * (a + v) + t;
        h = h > 0.f ? h : NEG_SLOPE * h;
        best = fmaxf(best, h);
    }
    g_H[(size_t)n * D + d] = best;
}

// ---------------- launch ----------------------------------------------------
extern "C" void kernel_launch(void* const* d_in, const int* in_sizes, int n_in,
                              void* d_out, int out_size) {
    const float* x      = (const float*)d_in[0];
    const float* center = (const float*)d_in[1];
    const float* w1     = (const float*)d_in[2];
    const float* w2     = (const float*)d_in[3];
    const float* bn1_g  = (const float*)d_in[4];
    const float* bn1_b  = (const float*)d_in[5];
    const float* bn1_m  = (const float*)d_in[6];
    const float* bn1_v  = (const float*)d_in[7];
    const float* bn2_g  = (const float*)d_in[8];
    const float* bn2_b  = (const float*)d_in[9];
    const float* bn2_m  = (const float*)d_in[10];
    const float* bn2_v  = (const float*)d_in[11];
    float* out = (float*)d_out;

    float *Yp, *Hp, *W1Bp;
    cudaGetSymbolAddress((void**)&Yp, g_Y);
    cudaGetSymbolAddress((void**)&Hp, g_H);
    cudaGetSymbolAddress((void**)&W1Bp, g_W1B);

    cudaFuncSetAttribute(mma_gemm_kernel<false>,
                         cudaFuncAttributeMaxDynamicSharedMemorySize, GEMM_SMEM);
    cudaFuncSetAttribute(mma_gemm_kernel<true>,
                         cudaFuncAttributeMaxDynamicSharedMemorySize, GEMM_SMEM);

    // 1. weight prep
    prep_weights_kernel<<<(TWO_D * D + 255) / 256, 256>>>(w1);

    // 2. KNN
    knn_kernel<<<dim3(N / 256, B), 256>>>(center);

    // 3. GEMM1: Y(16384x768) = X(16384x384) @ W1B^T
    mma_gemm_kernel<false><<<dim3(TWO_D / 128, BN_ROWS / 128), 256, GEMM_SMEM>>>(
        x, W1Bp, Yp, TWO_D, nullptr, nullptr, nullptr, nullptr);

    // 4. gather + BN1 + lrelu + max over K
    gather_max_kernel<<<BN_ROWS, D>>>(bn1_g, bn1_b, bn1_m, bn1_v);

    // 5. GEMM2: out = lrelu(bn2(H(16384x384) @ w2^T)), fused epilogue
    mma_gemm_kernel<true><<<dim3(D / 128, BN_ROWS / 128), 256, GEMM_SMEM>>>(
        Hp, w2, out, D, bn2_g, bn2_b, bn2_m, bn2_v);
}